// round 2
// baseline (speedup 1.0000x reference)
#include <cuda_runtime.h>
#include <cuda_fp16.h>
#include <cstdint>

// ---------------------------------------------------------------------------
// Problem dims (fixed by the dataset)
// ---------------------------------------------------------------------------
#define BATCH 8
#define TDIM 256
#define UDIM 64
#define ENC_DIM 512
#define PRED_DIM 640
#define JOINT_DIM 512
#define VOCAB 1024
#define MROWS (BATCH * TDIM * UDIM) // 131072

// ---------------------------------------------------------------------------
// Scratch (static __device__ arrays -- allocation-free per harness rules)
// ---------------------------------------------------------------------------
__device__ __align__(16) __half g_encH[BATCH * TDIM * ENC_DIM];     // 2 MB
__device__ __align__(16) __half g_predH[BATCH * UDIM * PRED_DIM];
__device__ __align__(16) __half g_WencH[ENC_DIM * JOINT_DIM];
__device__ __align__(16) __half g_WpredH[PRED_DIM * JOINT_DIM];
__device__ __align__(16) __half g_WjH[JOINT_DIM * VOCAB];
__device__ __align__(16) float  g_encP[BATCH * TDIM * JOINT_DIM];   // 4 MB
__device__ __align__(16) float  g_predP[BATCH * UDIM * JOINT_DIM];  // 1 MB
__device__ __align__(16) __half g_A[(size_t)MROWS * JOINT_DIM];     // 134 MB

// ---------------------------------------------------------------------------
// Helpers
// ---------------------------------------------------------------------------
__device__ __forceinline__ float tanh_ap(float x) {
    float y;
    asm("tanh.approx.f32 %0, %1;" : "=f"(y) : "f"(x));
    return y;
}

__device__ __forceinline__ void cp16(__half* s, const __half* g) {
    uint32_t sa = (uint32_t)__cvta_generic_to_shared(s);
    asm volatile("cp.async.cg.shared.global [%0], [%1], 16;\n" :: "r"(sa), "l"(g));
}

// ---------------------------------------------------------------------------
// Kernel 1: fp32 -> fp16 conversion of all operands (region-dispatched)
// Regions (in 1024-element blocks): enc 1024 | pred 320 | We 256 | Wp 320 | Wj 512
// ---------------------------------------------------------------------------
__global__ void convert_kernel(const float* __restrict__ enc,
                               const float* __restrict__ pred,
                               const float* __restrict__ we,
                               const float* __restrict__ wp,
                               const float* __restrict__ wj) {
    int blk = blockIdx.x;
    const float* src;
    __half* dst;
    int lb;
    if (blk < 1024)      { src = enc;  dst = g_encH;   lb = blk; }
    else if (blk < 1344) { src = pred; dst = g_predH;  lb = blk - 1024; }
    else if (blk < 1600) { src = we;   dst = g_WencH;  lb = blk - 1344; }
    else if (blk < 1920) { src = wp;   dst = g_WpredH; lb = blk - 1600; }
    else                 { src = wj;   dst = g_WjH;    lb = blk - 1920; }
    int idx = lb * 1024 + threadIdx.x * 4;
    float4 v = *reinterpret_cast<const float4*>(src + idx);
    __half2 h0 = __floats2half2_rn(v.x, v.y);
    __half2 h1 = __floats2half2_rn(v.z, v.w);
    uint2 o;
    o.x = *reinterpret_cast<uint32_t*>(&h0);
    o.y = *reinterpret_cast<uint32_t*>(&h1);
    *reinterpret_cast<uint2*>(dst + idx) = o;
}

// ---------------------------------------------------------------------------
// HGEMM: C[M,N] = A[M,K](f16) * B[K,N](f16) + bias[N], fp32 accumulate.
// CTA tile 128x128, 8 warps (2x4), warp tile 64x32, K-step 32, 3-stage cp.async.
// Padded smem: A_LD=40 halves/row, B_LD=136 halves/row (ldmatrix conflict-free).
// ---------------------------------------------------------------------------
#define KSTEP 32
#define STAGES 3
#define A_LD 40
#define B_LD 136
#define A_STG (128 * A_LD)   // 5120 halves
#define B_STG (KSTEP * B_LD) // 4352 halves
#define SMEM_BYTES ((STAGES * A_STG + STAGES * B_STG) * 2) // 56832

__device__ __forceinline__ void load_tile(const __half* __restrict__ A,
                                          const __half* __restrict__ Bm,
                                          int K, int N, int m0, int n0, int kt,
                                          __half* aS, __half* bS, int tid) {
    int k0 = kt * KSTEP;
#pragma unroll
    for (int i = 0; i < 2; i++) {
        int idx = tid + i * 256;
        int ar = idx >> 2, ac = (idx & 3) * 8;
        cp16(aS + ar * A_LD + ac, A + (size_t)(m0 + ar) * K + k0 + ac);
        int br = idx >> 4, bc = (idx & 15) * 8;
        cp16(bS + br * B_LD + bc, Bm + (size_t)(k0 + br) * N + n0 + bc);
    }
}

__global__ void __launch_bounds__(256, 2)
hgemm_kernel(const __half* __restrict__ A, const __half* __restrict__ Bm,
             const float* __restrict__ bias, float* __restrict__ C,
             int K, int N) {
    extern __shared__ __half smemBuf[];
    __half* aS = smemBuf;
    __half* bS = smemBuf + STAGES * A_STG;

    const int tid = threadIdx.x;
    const int lane = tid & 31;
    const int warp = tid >> 5;
    const int wm = warp >> 2;   // 0..1
    const int wn = warp & 3;    // 0..3
    const int m0 = blockIdx.y * 128;
    const int n0 = blockIdx.x * 128;
    const int kTiles = K / KSTEP;

    // prologue: prefetch STAGES-1 tiles
#pragma unroll
    for (int p = 0; p < STAGES - 1; p++) {
        load_tile(A, Bm, K, N, m0, n0, p, aS + p * A_STG, bS + p * B_STG, tid);
        asm volatile("cp.async.commit_group;\n");
    }

    float c[4][4][4];
#pragma unroll
    for (int m = 0; m < 4; m++)
#pragma unroll
        for (int n = 0; n < 4; n++)
#pragma unroll
            for (int r = 0; r < 4; r++) c[m][n][r] = 0.f;

    for (int kt = 0; kt < kTiles; ++kt) {
        asm volatile("cp.async.wait_group %0;\n" :: "n"(STAGES - 2));
        __syncthreads();

        int nx = kt + STAGES - 1;
        if (nx < kTiles)
            load_tile(A, Bm, K, N, m0, n0, nx,
                      aS + (nx % STAGES) * A_STG, bS + (nx % STAGES) * B_STG, tid);
        asm volatile("cp.async.commit_group;\n");

        const __half* a = aS + (kt % STAGES) * A_STG;
        const __half* b = bS + (kt % STAGES) * B_STG;

#pragma unroll
        for (int kk = 0; kk < 2; ++kk) {
            uint32_t af[4][4];
            uint32_t bf[2][4];
#pragma unroll
            for (int m = 0; m < 4; m++) {
                const __half* p = a + (wm * 64 + m * 16 + (lane & 15)) * A_LD
                                    + kk * 16 + (lane >> 4) * 8;
                uint32_t sa = (uint32_t)__cvta_generic_to_shared(p);
                asm volatile("ldmatrix.sync.aligned.m8n8.x4.shared.b16 {%0,%1,%2,%3}, [%4];\n"
                             : "=r"(af[m][0]), "=r"(af[m][1]), "=r"(af[m][2]), "=r"(af[m][3])
                             : "r"(sa));
            }
#pragma unroll
            for (int g = 0; g < 2; g++) {
                const __half* p = b + (kk * 16 + (lane & 15)) * B_LD
                                    + wn * 32 + g * 16 + (lane >> 4) * 8;
                uint32_t sa = (uint32_t)__cvta_generic_to_shared(p);
                asm volatile("ldmatrix.sync.aligned.m8n8.x4.trans.shared.b16 {%0,%1,%2,%3}, [%4];\n"
                             : "=r"(bf[g][0]), "=r"(bf[g][1]), "=r"(bf[g][2]), "=r"(bf[g][3])
                             : "r"(sa));
            }
#pragma unroll
            for (int m = 0; m < 4; m++) {
#pragma unroll
                for (int n = 0; n < 4; n++) {
                    uint32_t b0 = bf[n >> 1][(n & 1) * 2];
                    uint32_t b1 = bf[n >> 1][(n & 1) * 2 + 1];
                    asm volatile(
                        "mma.sync.aligned.m16n8k16.row.col.f32.f16.f16.f32 "
                        "{%0,%1,%2,%3}, {%4,%5,%6,%7}, {%8,%9}, {%0,%1,%2,%3};\n"
                        : "+f"(c[m][n][0]), "+f"(c[m][n][1]), "+f"(c[m][n][2]), "+f"(c[m][n][3])
                        : "r"(af[m][0]), "r"(af[m][1]), "r"(af[m][2]), "r"(af[m][3]),
                          "r"(b0), "r"(b1));
                }
            }
        }
    }

    // epilogue: add bias, streaming stores
    const int mb = m0 + wm * 64;
    const int nb = n0 + wn * 32;
    float2 bb[4];
#pragma unroll
    for (int n = 0; n < 4; n++) {
        int col = nb + n * 8 + (lane & 3) * 2;
        bb[n].x = bias[col];
        bb[n].y = bias[col + 1];
    }
#pragma unroll
    for (int m = 0; m < 4; m++) {
        int row = mb + m * 16 + (lane >> 2);
#pragma unroll
        for (int n = 0; n < 4; n++) {
            int col = nb + n * 8 + (lane & 3) * 2;
            float2 v0 = make_float2(c[m][n][0] + bb[n].x, c[m][n][1] + bb[n].y);
            float2 v1 = make_float2(c[m][n][2] + bb[n].x, c[m][n][3] + bb[n].y);
            __stcs(reinterpret_cast<float2*>(C + (size_t)row * N + col), v0);
            __stcs(reinterpret_cast<float2*>(C + (size_t)(row + 8) * N + col), v1);
        }
    }
}

// ---------------------------------------------------------------------------
// Kernel 3: joint = tanh(enc_p[b,t,:] + pred_p[b,u,:]) -> fp16 A matrix.
// One CTA per (b,t); enc row cached in smem; 64 u rows per CTA.
// ---------------------------------------------------------------------------
__global__ void __launch_bounds__(256) joint_tanh_kernel() {
    __shared__ float4 encS[JOINT_DIM / 4];
    const int bt = blockIdx.x;       // 0..2047
    const int tid = threadIdx.x;
    const int b = bt >> 8;

    const float4* encRow = reinterpret_cast<const float4*>(g_encP + (size_t)bt * JOINT_DIM);
    if (tid < JOINT_DIM / 4) encS[tid] = encRow[tid];
    __syncthreads();

#pragma unroll
    for (int i = 0; i < 16; i++) {
        int flat = i * 256 + tid;        // [0, 64*64)
        int u = flat >> 6;
        int j8 = (flat & 63) * 8;
        const float4* pp = reinterpret_cast<const float4*>(
            g_predP + (size_t)(b * UDIM + u) * JOINT_DIM + j8);
        float4 p0 = pp[0], p1 = pp[1];
        float4 e0 = encS[j8 >> 2];
        float4 e1 = encS[(j8 >> 2) + 1];
        __half2 h0 = __floats2half2_rn(tanh_ap(e0.x + p0.x), tanh_ap(e0.y + p0.y));
        __half2 h1 = __floats2half2_rn(tanh_ap(e0.z + p0.z), tanh_ap(e0.w + p0.w));
        __half2 h2 = __floats2half2_rn(tanh_ap(e1.x + p1.x), tanh_ap(e1.y + p1.y));
        __half2 h3 = __floats2half2_rn(tanh_ap(e1.z + p1.z), tanh_ap(e1.w + p1.w));
        uint4 o;
        o.x = *reinterpret_cast<uint32_t*>(&h0);
        o.y = *reinterpret_cast<uint32_t*>(&h1);
        o.z = *reinterpret_cast<uint32_t*>(&h2);
        o.w = *reinterpret_cast<uint32_t*>(&h3);
        *reinterpret_cast<uint4*>(g_A + ((size_t)bt * UDIM + u) * JOINT_DIM + j8) = o;
    }
}

// ---------------------------------------------------------------------------
// Launch
// ---------------------------------------------------------------------------
static void* sym_addr(const void* s) {
    void* p = nullptr;
    cudaGetSymbolAddress(&p, s);
    return p;
}

extern "C" void kernel_launch(void* const* d_in, const int* in_sizes, int n_in,
                              void* d_out, int out_size) {
    const float* enc_out = (const float*)d_in[0];
    const float* pred_out = (const float*)d_in[1];
    const float* W_enc = (const float*)d_in[2];
    const float* b_enc = (const float*)d_in[3];
    const float* W_pred = (const float*)d_in[4];
    const float* b_pred = (const float*)d_in[5];
    const float* W_joint = (const float*)d_in[6];
    const float* b_joint = (const float*)d_in[7];
    float* out = (float*)d_out;

    cudaFuncSetAttribute(hgemm_kernel,
                         cudaFuncAttributeMaxDynamicSharedMemorySize, SMEM_BYTES);

    __half* encH = (__half*)sym_addr(g_encH);
    __half* predH = (__half*)sym_addr(g_predH);
    __half* WencH = (__half*)sym_addr(g_WencH);
    __half* WpredH = (__half*)sym_addr(g_WpredH);
    __half* WjH = (__half*)sym_addr(g_WjH);
    float* encP = (float*)sym_addr(g_encP);
    float* predP = (float*)sym_addr(g_predP);
    __half* Amat = (__half*)sym_addr(g_A);

    // 1) convert everything to fp16
    convert_kernel<<<2432, 256>>>(enc_out, pred_out, W_enc, W_pred, W_joint);

    // 2) projections: enc_p = enc_out @ W_enc + b_enc ; pred_p likewise
    hgemm_kernel<<<dim3(JOINT_DIM / 128, (BATCH * TDIM) / 128), 256, SMEM_BYTES>>>(
        encH, WencH, b_enc, encP, ENC_DIM, JOINT_DIM);
    hgemm_kernel<<<dim3(JOINT_DIM / 128, (BATCH * UDIM) / 128), 256, SMEM_BYTES>>>(
        predH, WpredH, b_pred, predP, PRED_DIM, JOINT_DIM);

    // 3) joint tanh -> fp16 A (131072 x 512)
    joint_tanh_kernel<<<BATCH * TDIM, 256>>>();

    // 4) logits = A @ W_joint + b_joint  (131072 x 1024 x 512)
    hgemm_kernel<<<dim3(VOCAB / 128, MROWS / 128), 256, SMEM_BYTES>>>(
        Amat, WjH, b_joint, out, JOINT_DIM, VOCAB);
}